// round 2
// baseline (speedup 1.0000x reference)
#include <cuda_runtime.h>
#include <math.h>

#define N_MAX   200000
#define D       25
#define STRIDE  32
#define EPS     1e-5f

// ---------------- scratch (device globals; no allocation allowed) -----------
__device__ __align__(16) float g_hw[N_MAX * STRIDE];   // scaled h@W (source msgs) / pre-norm reuse
__device__ __align__(16) float g_acc[N_MAX * STRIDE];  // aggregation accumulator
__device__ float g_dinv[N_MAX];
__device__ int   g_deg[N_MAX];
__device__ float g_stats[256]; // layer1 @0: [0:25)=sum [32:57)=sumsq [64:89)=mu [96:121)=rsig ; layer2 @128

// vectorized L2 reduction (sm_90+): 4 floats per atomic op
__device__ __forceinline__ void red_add_v4(float* addr, float4 v) {
    asm volatile("red.global.add.v4.f32 [%0], {%1, %2, %3, %4};"
                 :: "l"(addr), "f"(v.x), "f"(v.y), "f"(v.z), "f"(v.w)
                 : "memory");
}

// ---------------- kernels ---------------------------------------------------

__global__ void k_zero(int n) {
    int i = blockIdx.x * blockDim.x + threadIdx.x;
    if (i < n)   g_deg[i] = 0;
    if (i < 256) g_stats[i] = 0.f;
}

__global__ void k_deg(const int* __restrict__ ei, int E) {
    int e = blockIdx.x * blockDim.x + threadIdx.x;
    if (e < E) atomicAdd(&g_deg[ei[E + e]], 1);
}

// gather emb[x], h@W1, scale by dinv, init accumulator with self-loop term
__global__ void k_node1(const int* __restrict__ x, const float* __restrict__ emb,
                        const float* __restrict__ W, int n) {
    __shared__ float ws[D * STRIDE];
    for (int i = threadIdx.x; i < D * STRIDE; i += blockDim.x) {
        int k = i / STRIDE, f = i % STRIDE;
        ws[i] = (f < D) ? W[k * D + f] : 0.f;
    }
    __syncthreads();
    int lane = threadIdx.x & 31;
    int node = blockIdx.x * (blockDim.x >> 5) + (threadIdx.x >> 5);
    if (node >= n) return;

    float dinv = rsqrtf((float)(g_deg[node] + 1));
    if (lane == 0) g_dinv[node] = dinv;

    int xi = x[node];
    float h = (lane < D) ? emb[xi * D + lane] : 0.f;

    float acc = 0.f;
#pragma unroll
    for (int k = 0; k < D; k++) {
        float hk = __shfl_sync(0xffffffffu, h, k);
        acc = fmaf(hk, ws[k * STRIDE + lane], acc);
    }
    float v = (lane < D) ? acc * dinv : 0.f;
    g_hw[node * STRIDE + lane]  = v;
    g_acc[node * STRIDE + lane] = v;   // self-loop contribution (dinv[i]*h; second dinv applied in fin)
}

// edge scatter: acc[dst] += hw_scaled[src]   (8 lanes per edge: 6x float4 + 1 scalar)
__global__ void k_scatter(const int* __restrict__ ei, int E) {
    long long gid = (long long)blockIdx.x * blockDim.x + threadIdx.x;
    int e = (int)(gid >> 3);
    if (e >= E) return;
    int lane = (int)(gid & 7);
    int s = ei[e];
    int d = ei[E + e];
    const float* srow = &g_hw[(long long)s * STRIDE];
    float*       drow = &g_acc[(long long)d * STRIDE];
    if (lane < 6) {
        float4 v = *(const float4*)(srow + lane * 4);
        red_add_v4(drow + lane * 4, v);
    } else if (lane == 6) {
        atomicAdd(drow + 24, srow[24]);
    }
}

// finalize conv: pre = dinv*acc + b ; accumulate per-feature sum & sumsq for batchnorm
__global__ void k_fin(const float* __restrict__ b, int off, int n) {
    __shared__ float ssum[D], ssq[D];
    if (threadIdx.x < D) { ssum[threadIdx.x] = 0.f; ssq[threadIdx.x] = 0.f; }
    __syncthreads();
    int lane = threadIdx.x & 31;
    int warp = threadIdx.x >> 5;
    int wpb  = blockDim.x >> 5;
    float bf = (lane < D) ? b[lane] : 0.f;
    float psum = 0.f, psq = 0.f;
    for (int node = blockIdx.x * wpb + warp; node < n; node += gridDim.x * wpb) {
        float dinv = g_dinv[node];
        float v = (lane < D) ? g_acc[node * STRIDE + lane] * dinv + bf : 0.f;
        g_hw[node * STRIDE + lane] = v;   // pre-norm activations (reuse buffer)
        psum += v;
        psq  = fmaf(v, v, psq);
    }
    if (lane < D) { atomicAdd(&ssum[lane], psum); atomicAdd(&ssq[lane], psq); }
    __syncthreads();
    if (threadIdx.x < D) {
        atomicAdd(&g_stats[off + threadIdx.x],      ssum[threadIdx.x]);
        atomicAdd(&g_stats[off + 32 + threadIdx.x], ssq[threadIdx.x]);
    }
}

__global__ void k_mustats(int off, int n) {
    int f = threadIdx.x;
    if (f < D) {
        float inv = 1.f / (float)n;
        float mu  = g_stats[off + f] * inv;
        float var = g_stats[off + 32 + f] * inv - mu * mu;
        g_stats[off + 64 + f] = mu;
        g_stats[off + 96 + f] = rsqrtf(var + EPS);
    }
}

// bn+relu of layer-1 output, then h@W2, scale by dinv, re-init accumulator
__global__ void k_node2(const float* __restrict__ W, const float* __restrict__ g,
                        const float* __restrict__ be, int off, int n) {
    __shared__ float ws[D * STRIDE];
    for (int i = threadIdx.x; i < D * STRIDE; i += blockDim.x) {
        int k = i / STRIDE, f = i % STRIDE;
        ws[i] = (f < D) ? W[k * D + f] : 0.f;
    }
    __syncthreads();
    int lane = threadIdx.x & 31;
    int node = blockIdx.x * (blockDim.x >> 5) + (threadIdx.x >> 5);
    if (node >= n) return;

    float h = 0.f;
    if (lane < D) {
        float pre = g_hw[node * STRIDE + lane];
        float t = (pre - g_stats[off + 64 + lane]) * g_stats[off + 96 + lane] * g[lane] + be[lane];
        h = fmaxf(t, 0.f);
    }
    float acc = 0.f;
#pragma unroll
    for (int k = 0; k < D; k++) {
        float hk = __shfl_sync(0xffffffffu, h, k);
        acc = fmaf(hk, ws[k * STRIDE + lane], acc);
    }
    float dinv = g_dinv[node];
    float v = (lane < D) ? acc * dinv : 0.f;
    g_hw[node * STRIDE + lane]  = v;
    g_acc[node * STRIDE + lane] = v;
}

// bn+relu of layer-2 output, MLP head (25->12 relu ->1), sigmoid
__global__ void k_final(const float* __restrict__ g, const float* __restrict__ be,
                        const float* __restrict__ Wm1, const float* __restrict__ bm1,
                        const float* __restrict__ Wm2, const float* __restrict__ bm2,
                        float* __restrict__ out, int off, int n) {
    __shared__ float wm[D * 16];
    for (int i = threadIdx.x; i < D * 16; i += blockDim.x) {
        int f = i >> 4, j = i & 15;
        wm[i] = (j < 12) ? Wm1[f * 12 + j] : 0.f;
    }
    __syncthreads();
    int lane = threadIdx.x & 31;
    int node = blockIdx.x * (blockDim.x >> 5) + (threadIdx.x >> 5);
    if (node >= n) return;

    float h = 0.f;
    if (lane < D) {
        float pre = g_hw[node * STRIDE + lane];
        float t = (pre - g_stats[off + 64 + lane]) * g_stats[off + 96 + lane] * g[lane] + be[lane];
        h = fmaxf(t, 0.f);
    }
    float m = 0.f;
#pragma unroll
    for (int f = 0; f < D; f++) {
        float hf = __shfl_sync(0xffffffffu, h, f);
        float w  = (lane < 16) ? wm[f * 16 + lane] : 0.f;
        m = fmaf(hf, w, m);
    }
    float t = 0.f;
    if (lane < 12) {
        m = fmaxf(m + bm1[lane], 0.f);
        t = m * Wm2[lane];
    }
#pragma unroll
    for (int o = 16; o > 0; o >>= 1) t += __shfl_down_sync(0xffffffffu, t, o);
    if (lane == 0) {
        float z = t + bm2[0];
        out[node] = 1.f / (1.f + __expf(-z));
    }
}

// ---------------- launch -----------------------------------------------------

extern "C" void kernel_launch(void* const* d_in, const int* in_sizes, int n_in,
                              void* d_out, int out_size) {
    const int*   x   = (const int*)d_in[0];
    const int*   ei  = (const int*)d_in[1];
    const float* emb = (const float*)d_in[2];
    const float* W1  = (const float*)d_in[3];
    const float* b1  = (const float*)d_in[4];
    const float* g1  = (const float*)d_in[5];
    const float* be1 = (const float*)d_in[6];
    const float* W2  = (const float*)d_in[7];
    const float* b2  = (const float*)d_in[8];
    const float* g2  = (const float*)d_in[9];
    const float* be2 = (const float*)d_in[10];
    const float* Wm1 = (const float*)d_in[11];
    const float* bm1 = (const float*)d_in[12];
    const float* Wm2 = (const float*)d_in[13];
    const float* bm2 = (const float*)d_in[14];
    float* out = (float*)d_out;

    int n = in_sizes[0];
    int E = in_sizes[1] / 2;

    int zb = (n + 255) / 256;
    int nodeBlocks = (n + 7) / 8;                       // 8 warps/block, 1 node/warp
    long long sthreads = (long long)E * 8;
    int sb = (int)((sthreads + 255) / 256);

    k_zero<<<zb, 256>>>(n);
    k_deg<<<(E + 255) / 256, 256>>>(ei, E);

    k_node1<<<nodeBlocks, 256>>>(x, emb, W1, n);
    k_scatter<<<sb, 256>>>(ei, E);
    k_fin<<<1184, 256>>>(b1, 0, n);
    k_mustats<<<1, 32>>>(0, n);

    k_node2<<<nodeBlocks, 256>>>(W2, g1, be1, 0, n);
    k_scatter<<<sb, 256>>>(ei, E);
    k_fin<<<1184, 256>>>(b2, 128, n);
    k_mustats<<<1, 32>>>(128, n);

    k_final<<<nodeBlocks, 256>>>(g2, be2, Wm1, bm1, Wm2, bm2, out, 128, n);
}

// round 3
// speedup vs baseline: 1.1890x; 1.1890x over previous
#include <cuda_runtime.h>
#include <math.h>

#define N_MAX   200000
#define E_MAX   3200000
#define D       25
#define STRIDE  32
#define EPS     1e-5f

// ---------------- scratch (device globals; no allocation allowed) -----------
__device__ __align__(16) float g_hw[(N_MAX + 1) * STRIDE];   // scaled h@W (source msgs); row N_MAX = zero pad
__device__ __align__(16) float g_pre[N_MAX * STRIDE];        // pre-batchnorm activations
__device__ int   g_csr[E_MAX];     // source ids grouped by destination
__device__ int   g_off[N_MAX];     // start of each destination's group
__device__ int   g_cur[N_MAX];     // fill cursors
__device__ int   g_deg[N_MAX];
__device__ float g_dinv[N_MAX];
__device__ int   g_total;
__device__ float g_stats[256]; // L1 @0: [0:25)=sum [32:57)=sumsq [64:89)=mu [96:121)=rsig ; L2 @128

// ---------------- kernels ---------------------------------------------------

__global__ void k_zero(int n) {
    int i = blockIdx.x * blockDim.x + threadIdx.x;
    if (i < n)   g_deg[i] = 0;
    if (i < 256) g_stats[i] = 0.f;
    if (i == 0)  g_total = 0;
    if (i < STRIDE) g_hw[n * STRIDE + i] = 0.f;   // zero pad row for gather padding
}

__global__ void k_deg(const int* __restrict__ ei, int E) {
    int e = blockIdx.x * blockDim.x + threadIdx.x;
    if (e < E) atomicAdd(&g_deg[ei[E + e]], 1);
}

// allocate contiguous CSR ranges per node (warp scan + one atomic per warp)
__global__ void k_off(int n) {
    int i = blockIdx.x * blockDim.x + threadIdx.x;
    int lane = threadIdx.x & 31;
    int d = (i < n) ? g_deg[i] : 0;
    int pref = d;
#pragma unroll
    for (int o = 1; o < 32; o <<= 1) {
        int t = __shfl_up_sync(0xffffffffu, pref, o);
        if (lane >= o) pref += t;
    }
    int total = __shfl_sync(0xffffffffu, pref, 31);
    int base = 0;
    if (lane == 0) base = atomicAdd(&g_total, total);
    base = __shfl_sync(0xffffffffu, base, 0);
    if (i < n) {
        int b = base + pref - d;
        g_off[i] = b;
        g_cur[i] = b;
    }
}

__global__ void k_fill(const int* __restrict__ ei, int E) {
    int e = blockIdx.x * blockDim.x + threadIdx.x;
    if (e < E) {
        int s = ei[e];
        int d = ei[E + e];
        int p = atomicAdd(&g_cur[d], 1);
        g_csr[p] = s;
    }
}

// gather emb[x], h@W1, scale by dinv[node]
__global__ void k_node1(const int* __restrict__ x, const float* __restrict__ emb,
                        const float* __restrict__ W, int n) {
    __shared__ float ws[D * STRIDE];
    for (int i = threadIdx.x; i < D * STRIDE; i += blockDim.x) {
        int k = i / STRIDE, f = i % STRIDE;
        ws[i] = (f < D) ? W[k * D + f] : 0.f;
    }
    __syncthreads();
    int lane = threadIdx.x & 31;
    int node = blockIdx.x * (blockDim.x >> 5) + (threadIdx.x >> 5);
    if (node >= n) return;

    float dinv = rsqrtf((float)(g_deg[node] + 1));
    if (lane == 0) g_dinv[node] = dinv;

    int xi = x[node];
    float h = (lane < D) ? emb[xi * D + lane] : 0.f;

    float acc = 0.f;
#pragma unroll
    for (int k = 0; k < D; k++) {
        float hk = __shfl_sync(0xffffffffu, h, k);
        acc = fmaf(hk, ws[k * STRIDE + lane], acc);
    }
    g_hw[node * STRIDE + lane] = (lane < D) ? acc * dinv : 0.f;
}

// warp-per-node gather aggregation + finalize (dinv*sum + b) + BN stats
__global__ void k_agg(const float* __restrict__ b, int off, int n, int npad) {
    __shared__ float ssum[32], ssq[32];
    if (threadIdx.x < 32) { ssum[threadIdx.x] = 0.f; ssq[threadIdx.x] = 0.f; }
    __syncthreads();
    int lane = threadIdx.x & 31;
    int warp = threadIdx.x >> 5;
    int wpb  = blockDim.x >> 5;
    float bf = (lane < D) ? b[lane] : 0.f;
    float psum = 0.f, psq = 0.f;

    for (int node = blockIdx.x * wpb + warp; node < n; node += gridDim.x * wpb) {
        int beg = g_off[node];
        int cnt = g_deg[node];
        float acc = g_hw[node * STRIDE + lane];   // self-loop term
        for (int j0 = 0; j0 < cnt; j0 += 32) {
            int idx = npad;   // pad row (zeros)
            if (j0 + lane < cnt) idx = g_csr[beg + j0 + lane];
            int m = cnt - j0; if (m > 32) m = 32;
#pragma unroll 4
            for (int t = 0; t < m; t++) {
                int j = __shfl_sync(0xffffffffu, idx, t);
                acc += g_hw[j * STRIDE + lane];
            }
        }
        float dinv = g_dinv[node];
        float v = acc * dinv + bf;                // lanes>=D: acc=0, bf=0 -> 0
        g_pre[node * STRIDE + lane] = v;
        psum += v;
        psq  = fmaf(v, v, psq);
    }
    if (lane < D) { atomicAdd(&ssum[lane], psum); atomicAdd(&ssq[lane], psq); }
    __syncthreads();
    if (threadIdx.x < D) {
        atomicAdd(&g_stats[off + threadIdx.x],      ssum[threadIdx.x]);
        atomicAdd(&g_stats[off + 32 + threadIdx.x], ssq[threadIdx.x]);
    }
}

__global__ void k_mustats(int off, int n) {
    int f = threadIdx.x;
    if (f < D) {
        float inv = 1.f / (float)n;
        float mu  = g_stats[off + f] * inv;
        float var = g_stats[off + 32 + f] * inv - mu * mu;
        g_stats[off + 64 + f] = mu;
        g_stats[off + 96 + f] = rsqrtf(var + EPS);
    }
}

// bn+relu of layer-1 output, then h@W2, scale by dinv
__global__ void k_node2(const float* __restrict__ W, const float* __restrict__ g,
                        const float* __restrict__ be, int off, int n) {
    __shared__ float ws[D * STRIDE];
    for (int i = threadIdx.x; i < D * STRIDE; i += blockDim.x) {
        int k = i / STRIDE, f = i % STRIDE;
        ws[i] = (f < D) ? W[k * D + f] : 0.f;
    }
    __syncthreads();
    int lane = threadIdx.x & 31;
    int node = blockIdx.x * (blockDim.x >> 5) + (threadIdx.x >> 5);
    if (node >= n) return;

    float h = 0.f;
    if (lane < D) {
        float pre = g_pre[node * STRIDE + lane];
        float t = (pre - g_stats[off + 64 + lane]) * g_stats[off + 96 + lane] * g[lane] + be[lane];
        h = fmaxf(t, 0.f);
    }
    float acc = 0.f;
#pragma unroll
    for (int k = 0; k < D; k++) {
        float hk = __shfl_sync(0xffffffffu, h, k);
        acc = fmaf(hk, ws[k * STRIDE + lane], acc);
    }
    float dinv = g_dinv[node];
    g_hw[node * STRIDE + lane] = (lane < D) ? acc * dinv : 0.f;
}

// bn+relu of layer-2 output, MLP head (25->12 relu ->1), sigmoid
__global__ void k_final(const float* __restrict__ g, const float* __restrict__ be,
                        const float* __restrict__ Wm1, const float* __restrict__ bm1,
                        const float* __restrict__ Wm2, const float* __restrict__ bm2,
                        float* __restrict__ out, int off, int n) {
    __shared__ float wm[D * 16];
    for (int i = threadIdx.x; i < D * 16; i += blockDim.x) {
        int f = i >> 4, j = i & 15;
        wm[i] = (j < 12) ? Wm1[f * 12 + j] : 0.f;
    }
    __syncthreads();
    int lane = threadIdx.x & 31;
    int node = blockIdx.x * (blockDim.x >> 5) + (threadIdx.x >> 5);
    if (node >= n) return;

    float h = 0.f;
    if (lane < D) {
        float pre = g_pre[node * STRIDE + lane];
        float t = (pre - g_stats[off + 64 + lane]) * g_stats[off + 96 + lane] * g[lane] + be[lane];
        h = fmaxf(t, 0.f);
    }
    float m = 0.f;
#pragma unroll
    for (int f = 0; f < D; f++) {
        float hf = __shfl_sync(0xffffffffu, h, f);
        float w  = (lane < 16) ? wm[f * 16 + lane] : 0.f;
        m = fmaf(hf, w, m);
    }
    float t = 0.f;
    if (lane < 12) {
        m = fmaxf(m + bm1[lane], 0.f);
        t = m * Wm2[lane];
    }
#pragma unroll
    for (int o = 16; o > 0; o >>= 1) t += __shfl_down_sync(0xffffffffu, t, o);
    if (lane == 0) {
        float z = t + bm2[0];
        out[node] = 1.f / (1.f + __expf(-z));
    }
}

// ---------------- launch -----------------------------------------------------

extern "C" void kernel_launch(void* const* d_in, const int* in_sizes, int n_in,
                              void* d_out, int out_size) {
    const int*   x   = (const int*)d_in[0];
    const int*   ei  = (const int*)d_in[1];
    const float* emb = (const float*)d_in[2];
    const float* W1  = (const float*)d_in[3];
    const float* b1  = (const float*)d_in[4];
    const float* g1  = (const float*)d_in[5];
    const float* be1 = (const float*)d_in[6];
    const float* W2  = (const float*)d_in[7];
    const float* b2  = (const float*)d_in[8];
    const float* g2  = (const float*)d_in[9];
    const float* be2 = (const float*)d_in[10];
    const float* Wm1 = (const float*)d_in[11];
    const float* bm1 = (const float*)d_in[12];
    const float* Wm2 = (const float*)d_in[13];
    const float* bm2 = (const float*)d_in[14];
    float* out = (float*)d_out;

    int n = in_sizes[0];
    int E = in_sizes[1] / 2;

    int zb = (n + 255) / 256;
    int eb = (E + 255) / 256;
    int nodeBlocks = (n + 7) / 8;    // 8 warps/block, 1 node/warp

    k_zero<<<zb, 256>>>(n);
    k_deg<<<eb, 256>>>(ei, E);
    k_off<<<zb, 256>>>(n);
    k_fill<<<eb, 256>>>(ei, E);

    k_node1<<<nodeBlocks, 256>>>(x, emb, W1, n);
    k_agg<<<1184, 256>>>(b1, 0, n, n);
    k_mustats<<<1, 32>>>(0, n);

    k_node2<<<nodeBlocks, 256>>>(W2, g1, be1, 0, n);
    k_agg<<<1184, 256>>>(b2, 128, n, n);
    k_mustats<<<1, 32>>>(128, n);

    k_final<<<nodeBlocks, 256>>>(g2, be2, Wm1, bm1, Wm2, bm2, out, 128, n);
}

// round 6
// speedup vs baseline: 1.2616x; 1.0610x over previous
#include <cuda_runtime.h>
#include <math.h>

#define N_MAX   200000
#define E_MAX   3200000
#define D       25
#define STRIDE  32
#define EPS     1e-5f

// ---------------- scratch (device globals; no allocation allowed) -----------
__device__ __align__(16) float g_hw[N_MAX * STRIDE];   // scaled h@W (source msgs)
__device__ __align__(16) float g_pre[N_MAX * STRIDE];  // pre-batchnorm activations
__device__ int   g_csr[E_MAX];     // source ids grouped by destination
__device__ int   g_off[N_MAX];     // start of each destination's group
__device__ int   g_cur[N_MAX];     // fill cursors
__device__ int   g_deg[N_MAX];
__device__ float g_dinv[N_MAX];
__device__ int   g_total;
__device__ float g_stats[256]; // L1 @0: [0:25)=sum [32:57)=sumsq [64:89)=mu [96:121)=rsig ; L2 @128

// ---------------- kernels ---------------------------------------------------

__global__ void k_zero(int n) {
    int i = blockIdx.x * blockDim.x + threadIdx.x;
    if (i < n)   g_deg[i] = 0;
    if (i < 256) g_stats[i] = 0.f;
    if (i == 0)  g_total = 0;
}

// 2 edges per thread, vectorized index reads
__global__ void k_deg(const int* __restrict__ ei, int E) {
    int t = blockIdx.x * blockDim.x + threadIdx.x;
    int e = t * 2;
    if (e + 1 < E) {
        int2 d = *(const int2*)(ei + E + e);
        atomicAdd(&g_deg[d.x], 1);
        atomicAdd(&g_deg[d.y], 1);
    } else if (e < E) {
        atomicAdd(&g_deg[ei[E + e]], 1);
    }
}

// allocate contiguous CSR ranges per node (warp scan + one atomic per warp)
__global__ void k_off(int n) {
    int i = blockIdx.x * blockDim.x + threadIdx.x;
    int lane = threadIdx.x & 31;
    int d = (i < n) ? g_deg[i] : 0;
    int pref = d;
#pragma unroll
    for (int o = 1; o < 32; o <<= 1) {
        int t = __shfl_up_sync(0xffffffffu, pref, o);
        if (lane >= o) pref += t;
    }
    int total = __shfl_sync(0xffffffffu, pref, 31);
    int base = 0;
    if (lane == 0) base = atomicAdd(&g_total, total);
    base = __shfl_sync(0xffffffffu, base, 0);
    if (i < n) {
        int b = base + pref - d;
        g_off[i] = b;
        g_cur[i] = b;
    }
}

// 2 edges per thread, vectorized index reads
__global__ void k_fill(const int* __restrict__ ei, int E) {
    int t = blockIdx.x * blockDim.x + threadIdx.x;
    int e = t * 2;
    if (e + 1 < E) {
        int2 s = *(const int2*)(ei + e);
        int2 d = *(const int2*)(ei + E + e);
        int p0 = atomicAdd(&g_cur[d.x], 1);
        int p1 = atomicAdd(&g_cur[d.y], 1);
        g_csr[p0] = s.x;
        g_csr[p1] = s.y;
    } else if (e < E) {
        int p = atomicAdd(&g_cur[ei[E + e]], 1);
        g_csr[p] = ei[e];
    }
}

// gather emb[x], h@W1, scale by dinv[node]
__global__ void k_node1(const int* __restrict__ x, const float* __restrict__ emb,
                        const float* __restrict__ W, int n) {
    __shared__ float ws[D * STRIDE];
    for (int i = threadIdx.x; i < D * STRIDE; i += blockDim.x) {
        int k = i / STRIDE, f = i % STRIDE;
        ws[i] = (f < D) ? W[k * D + f] : 0.f;
    }
    __syncthreads();
    int lane = threadIdx.x & 31;
    int node = blockIdx.x * (blockDim.x >> 5) + (threadIdx.x >> 5);
    if (node >= n) return;

    float dinv = rsqrtf((float)(g_deg[node] + 1));
    if (lane == 0) g_dinv[node] = dinv;

    int xi = x[node];
    float h = (lane < D) ? emb[xi * D + lane] : 0.f;

    float acc = 0.f;
#pragma unroll
    for (int k = 0; k < D; k++) {
        float hk = __shfl_sync(0xffffffffu, h, k);
        acc = fmaf(hk, ws[k * STRIDE + lane], acc);
    }
    g_hw[node * STRIDE + lane] = (lane < D) ? acc * dinv : 0.f;
}

// gather aggregation: 8 threads per node, float4 per thread.
// No shfl in the address path; 4 independent LDG.128 in flight per thread.
__global__ void k_agg(const float* __restrict__ b, int off, int n) {
    __shared__ float sb[32];
    __shared__ float ssum[32], ssq[32];
    if (threadIdx.x < 32) {
        sb[threadIdx.x]   = (threadIdx.x < D) ? b[threadIdx.x] : 0.f;
        ssum[threadIdx.x] = 0.f;
        ssq[threadIdx.x]  = 0.f;
    }
    __syncthreads();

    int sub = threadIdx.x & 7;        // float4 slot within row (feature group)
    int grp = threadIdx.x >> 3;       // node slot within block
    int gpb = blockDim.x >> 3;
    const float4* base = (const float4*)g_hw;
    float4* preb = (float4*)g_pre;
    float4 bf = ((const float4*)sb)[sub];
    float4 psum = make_float4(0.f, 0.f, 0.f, 0.f);
    float4 psq  = make_float4(0.f, 0.f, 0.f, 0.f);

    for (int node = blockIdx.x * gpb + grp; node < n; node += gridDim.x * gpb) {
        int beg = g_off[node];
        int cnt = g_deg[node];
        float4 acc = base[node * 8 + sub];   // self-loop term (already dinv-scaled at source)
        int j = 0;
        for (; j + 4 <= cnt; j += 4) {
            int i0 = __ldg(&g_csr[beg + j]);
            int i1 = __ldg(&g_csr[beg + j + 1]);
            int i2 = __ldg(&g_csr[beg + j + 2]);
            int i3 = __ldg(&g_csr[beg + j + 3]);
            float4 v0 = base[i0 * 8 + sub];
            float4 v1 = base[i1 * 8 + sub];
            float4 v2 = base[i2 * 8 + sub];
            float4 v3 = base[i3 * 8 + sub];
            acc.x += v0.x + v1.x + v2.x + v3.x;
            acc.y += v0.y + v1.y + v2.y + v3.y;
            acc.z += v0.z + v1.z + v2.z + v3.z;
            acc.w += v0.w + v1.w + v2.w + v3.w;
        }
        for (; j < cnt; j++) {
            int i0 = __ldg(&g_csr[beg + j]);
            float4 v0 = base[i0 * 8 + sub];
            acc.x += v0.x; acc.y += v0.y; acc.z += v0.z; acc.w += v0.w;
        }
        float dinv = g_dinv[node];
        float4 v;
        v.x = fmaf(acc.x, dinv, bf.x);
        v.y = fmaf(acc.y, dinv, bf.y);
        v.z = fmaf(acc.z, dinv, bf.z);
        v.w = fmaf(acc.w, dinv, bf.w);
        preb[node * 8 + sub] = v;
        psum.x += v.x; psum.y += v.y; psum.z += v.z; psum.w += v.w;
        psq.x = fmaf(v.x, v.x, psq.x); psq.y = fmaf(v.y, v.y, psq.y);
        psq.z = fmaf(v.z, v.z, psq.z); psq.w = fmaf(v.w, v.w, psq.w);
    }

    int f = sub * 4;
    atomicAdd(&ssum[f + 0], psum.x); atomicAdd(&ssum[f + 1], psum.y);
    atomicAdd(&ssum[f + 2], psum.z); atomicAdd(&ssum[f + 3], psum.w);
    atomicAdd(&ssq[f + 0], psq.x);   atomicAdd(&ssq[f + 1], psq.y);
    atomicAdd(&ssq[f + 2], psq.z);   atomicAdd(&ssq[f + 3], psq.w);
    __syncthreads();
    if (threadIdx.x < D) {
        atomicAdd(&g_stats[off + threadIdx.x],      ssum[threadIdx.x]);
        atomicAdd(&g_stats[off + 32 + threadIdx.x], ssq[threadIdx.x]);
    }
}

__global__ void k_mustats(int off, int n) {
    int f = threadIdx.x;
    if (f < D) {
        float inv = 1.f / (float)n;
        float mu  = g_stats[off + f] * inv;
        float var = g_stats[off + 32 + f] * inv - mu * mu;
        g_stats[off + 64 + f] = mu;
        g_stats[off + 96 + f] = rsqrtf(var + EPS);
    }
}

// bn+relu of layer-1 output, then h@W2, scale by dinv
__global__ void k_node2(const float* __restrict__ W, const float* __restrict__ g,
                        const float* __restrict__ be, int off, int n) {
    __shared__ float ws[D * STRIDE];
    for (int i = threadIdx.x; i < D * STRIDE; i += blockDim.x) {
        int k = i / STRIDE, f = i % STRIDE;
        ws[i] = (f < D) ? W[k * D + f] : 0.f;
    }
    __syncthreads();
    int lane = threadIdx.x & 31;
    int node = blockIdx.x * (blockDim.x >> 5) + (threadIdx.x >> 5);
    if (node >= n) return;

    float h = 0.f;
    if (lane < D) {
        float pre = g_pre[node * STRIDE + lane];
        float t = (pre - g_stats[off + 64 + lane]) * g_stats[off + 96 + lane] * g[lane] + be[lane];
        h = fmaxf(t, 0.f);
    }
    float acc = 0.f;
#pragma unroll
    for (int k = 0; k < D; k++) {
        float hk = __shfl_sync(0xffffffffu, h, k);
        acc = fmaf(hk, ws[k * STRIDE + lane], acc);
    }
    float dinv = g_dinv[node];
    g_hw[node * STRIDE + lane] = (lane < D) ? acc * dinv : 0.f;
}

// bn+relu of layer-2 output, MLP head (25->12 relu ->1), sigmoid
__global__ void k_final(const float* __restrict__ g, const float* __restrict__ be,
                        const float* __restrict__ Wm1, const float* __restrict__ bm1,
                        const float* __restrict__ Wm2, const float* __restrict__ bm2,
                        float* __restrict__ out, int off, int n) {
    __shared__ float wm[D * 16];
    for (int i = threadIdx.x; i < D * 16; i += blockDim.x) {
        int f = i >> 4, j = i & 15;
        wm[i] = (j < 12) ? Wm1[f * 12 + j] : 0.f;
    }
    __syncthreads();
    int lane = threadIdx.x & 31;
    int node = blockIdx.x * (blockDim.x >> 5) + (threadIdx.x >> 5);
    if (node >= n) return;

    float h = 0.f;
    if (lane < D) {
        float pre = g_pre[node * STRIDE + lane];
        float t = (pre - g_stats[off + 64 + lane]) * g_stats[off + 96 + lane] * g[lane] + be[lane];
        h = fmaxf(t, 0.f);
    }
    float m = 0.f;
#pragma unroll
    for (int f = 0; f < D; f++) {
        float hf = __shfl_sync(0xffffffffu, h, f);
        float w  = (lane < 16) ? wm[f * 16 + lane] : 0.f;
        m = fmaf(hf, w, m);
    }
    float t = 0.f;
    if (lane < 12) {
        m = fmaxf(m + bm1[lane], 0.f);
        t = m * Wm2[lane];
    }
#pragma unroll
    for (int o = 16; o > 0; o >>= 1) t += __shfl_down_sync(0xffffffffu, t, o);
    if (lane == 0) {
        float z = t + bm2[0];
        out[node] = 1.f / (1.f + __expf(-z));
    }
}

// ---------------- launch -----------------------------------------------------

extern "C" void kernel_launch(void* const* d_in, const int* in_sizes, int n_in,
                              void* d_out, int out_size) {
    const int*   x   = (const int*)d_in[0];
    const int*   ei  = (const int*)d_in[1];
    const float* emb = (const float*)d_in[2];
    const float* W1  = (const float*)d_in[3];
    const float* b1  = (const float*)d_in[4];
    const float* g1  = (const float*)d_in[5];
    const float* be1 = (const float*)d_in[6];
    const float* W2  = (const float*)d_in[7];
    const float* b2  = (const float*)d_in[8];
    const float* g2  = (const float*)d_in[9];
    const float* be2 = (const float*)d_in[10];
    const float* Wm1 = (const float*)d_in[11];
    const float* bm1 = (const float*)d_in[12];
    const float* Wm2 = (const float*)d_in[13];
    const float* bm2 = (const float*)d_in[14];
    float* out = (float*)d_out;

    int n = in_sizes[0];
    int E = in_sizes[1] / 2;

    int zb = (n + 255) / 256;
    int eb2 = ((E + 1) / 2 + 255) / 256;   // 2 edges/thread
    int nodeBlocks = (n + 7) / 8;          // 8 warps/block, 1 node/warp

    k_zero<<<zb, 256>>>(n);
    k_deg<<<eb2, 256>>>(ei, E);
    k_off<<<zb, 256>>>(n);
    k_fill<<<eb2, 256>>>(ei, E);

    k_node1<<<nodeBlocks, 256>>>(x, emb, W1, n);
    k_agg<<<1184, 256>>>(b1, 0, n);
    k_mustats<<<1, 32>>>(0, n);

    k_node2<<<nodeBlocks, 256>>>(W2, g1, be1, 0, n);
    k_agg<<<1184, 256>>>(b2, 128, n);
    k_mustats<<<1, 32>>>(128, n);

    k_final<<<nodeBlocks, 256>>>(g2, be2, Wm1, bm1, Wm2, bm2, out, 128, n);
}